// round 1
// baseline (speedup 1.0000x reference)
#include <cuda_runtime.h>

#define NHEAD 8
#define HD 64
#define DMODEL 512
#define NP 16
#define NB 2
#define NT 2048
#define NVOC 16
#define NTOK (NB*NT)        // 4096
#define NTH (NTOK*NHEAD)    // 32768

// ---------------- scratch (no allocations allowed) ----------------
__device__ float g_x[NTOK*DMODEL];     // embedding output (residual)
__device__ float g_h[NTOK*DMODEL];     // layernorm output
__device__ float g_q[NTH*HD];
__device__ float g_k[NTH*HD];
__device__ float g_v[NTH*HD];
__device__ float g_attn[NTH*HD];
__device__ float g_C[DMODEL*NVOC];     // o_w^T @ head_w^T

// ---------------- K0: C[d][v] = sum_e o_w[e,d]*head_w[v,e] ----------------
__global__ void k_compute_C(const float* __restrict__ o_w,
                            const float* __restrict__ head_w) {
    int idx = blockIdx.x * blockDim.x + threadIdx.x;   // 8192 threads
    if (idx >= DMODEL * NVOC) return;
    int d = idx >> 4, v = idx & 15;
    float acc = 0.f;
    #pragma unroll 8
    for (int e = 0; e < DMODEL; ++e)
        acc += o_w[e * DMODEL + d] * head_w[v * DMODEL + e];
    g_C[d * NVOC + v] = acc;
}

// ---------------- K1: embedding + layernorm ----------------
__global__ __launch_bounds__(128) void k_embed_ln(
    const int* __restrict__ ids, const float* __restrict__ embed,
    const float* __restrict__ lng, const float* __restrict__ lnb) {
    int t = blockIdx.x;
    int tid = threadIdx.x;   // 128 threads x float4 = 512
    const float4* row = (const float4*)(embed + (size_t)ids[t] * DMODEL);
    float4 xv = row[tid];
    float s  = xv.x + xv.y + xv.z + xv.w;
    float s2 = xv.x*xv.x + xv.y*xv.y + xv.z*xv.z + xv.w*xv.w;
    #pragma unroll
    for (int o = 16; o; o >>= 1) {
        s  += __shfl_xor_sync(0xffffffffu, s, o);
        s2 += __shfl_xor_sync(0xffffffffu, s2, o);
    }
    __shared__ float sh[8];
    int w = tid >> 5;
    if ((tid & 31) == 0) { sh[w] = s; sh[4 + w] = s2; }
    __syncthreads();
    s  = sh[0] + sh[1] + sh[2] + sh[3];
    s2 = sh[4] + sh[5] + sh[6] + sh[7];
    float mu  = s * (1.0f / DMODEL);
    float var = s2 * (1.0f / DMODEL) - mu * mu;
    float inv = rsqrtf(var + 1e-5f);
    float4 gv = ((const float4*)lng)[tid];
    float4 bv = ((const float4*)lnb)[tid];
    float4 hv;
    hv.x = (xv.x - mu) * inv * gv.x + bv.x;
    hv.y = (xv.y - mu) * inv * gv.y + bv.y;
    hv.z = (xv.z - mu) * inv * gv.z + bv.z;
    hv.w = (xv.w - mu) * inv * gv.w + bv.w;
    ((float4*)(g_x + (size_t)t * DMODEL))[tid] = xv;
    ((float4*)(g_h + (size_t)t * DMODEL))[tid] = hv;
}

// ---------------- K2: shared expert MLP + 3-way gated combine ----------------
// Block: 256 threads, 64 token-head rows. smem GEMMs 64x64x64, 4x4 reg tiles.
__global__ __launch_bounds__(256, 2) void k_compose(
    const float* __restrict__ pq, const float* __restrict__ gq,
    const float* __restrict__ pk, const float* __restrict__ gk,
    const float* __restrict__ pv, const float* __restrict__ gv,
    const float* __restrict__ w1, const float* __restrict__ w2) {
    extern __shared__ float sm[];
    float* Xs = sm;                   // [64][65]
    float* Ws = sm + 64 * 65;         // [64][65]
    float* Ss = sm + 2 * 64 * 65;     // [64][65]
    float* WG = sm + 3 * 64 * 65;     // [3][64][16]
    const int tid  = threadIdx.x;
    const int row0 = blockIdx.x * 64;

    for (int i = tid; i < 64 * 64; i += 256) {
        int r = i >> 6, c = i & 63;
        Xs[r * 65 + c] = g_h[(size_t)(row0 + r) * 64 + c];
    }
    __syncthreads();

    // gate weights: relu(dot(x,proto)/8 - gate), zeroed below 1e-6
    for (int i = tid; i < 64 * 16; i += 256) {
        int r = i >> 4, p = i & 15;
        float dq = 0.f, dk = 0.f, dv = 0.f;
        #pragma unroll 8
        for (int d = 0; d < 64; ++d) {
            float xv = Xs[r * 65 + d];
            dq += xv * pq[p * 64 + d];
            dk += xv * pk[p * 64 + d];
            dv += xv * pv[p * 64 + d];
        }
        float lq = dq * 0.125f - gq[p];
        float lk = dk * 0.125f - gk[p];
        float lv = dv * 0.125f - gv[p];
        WG[(0 * 64 + r) * 16 + p] = lq > 1e-6f ? lq : 0.f;
        WG[(1 * 64 + r) * 16 + p] = lk > 1e-6f ? lk : 0.f;
        WG[(2 * 64 + r) * 16 + p] = lv > 1e-6f ? lv : 0.f;
    }

    const int ty = tid >> 4, tx = tid & 15;
    const int r0 = ty * 4, c0 = tx * 4;
    float aq[16], ak[16], av[16];
    #pragma unroll
    for (int i = 0; i < 16; ++i) { aq[i] = 0.f; ak[i] = 0.f; av[i] = 0.f; }

    for (int p = 0; p < NP; ++p) {
        __syncthreads();
        for (int i = tid; i < 4096; i += 256)
            Ws[(i >> 6) * 65 + (i & 63)] = w1[p * 4096 + i];
        __syncthreads();

        float acc[16];
        #pragma unroll
        for (int i = 0; i < 16; ++i) acc[i] = 0.f;
        #pragma unroll 4
        for (int d = 0; d < 64; ++d) {
            float a0 = Xs[(r0+0)*65+d], a1 = Xs[(r0+1)*65+d];
            float a2 = Xs[(r0+2)*65+d], a3 = Xs[(r0+3)*65+d];
            float b0 = Ws[(c0+0)*65+d], b1 = Ws[(c0+1)*65+d];
            float b2 = Ws[(c0+2)*65+d], b3 = Ws[(c0+3)*65+d];
            acc[0]  += a0*b0; acc[1]  += a0*b1; acc[2]  += a0*b2; acc[3]  += a0*b3;
            acc[4]  += a1*b0; acc[5]  += a1*b1; acc[6]  += a1*b2; acc[7]  += a1*b3;
            acc[8]  += a2*b0; acc[9]  += a2*b1; acc[10] += a2*b2; acc[11] += a2*b3;
            acc[12] += a3*b0; acc[13] += a3*b1; acc[14] += a3*b2; acc[15] += a3*b3;
        }
        // silu -> Ss
        #pragma unroll
        for (int i = 0; i < 4; ++i)
            #pragma unroll
            for (int j = 0; j < 4; ++j) {
                float hv = acc[i * 4 + j];
                Ss[(r0 + i) * 65 + (c0 + j)] = hv / (1.f + __expf(-hv));
            }
        __syncthreads();
        for (int i = tid; i < 4096; i += 256)
            Ws[(i >> 6) * 65 + (i & 63)] = w2[p * 4096 + i];
        __syncthreads();

        float occ[16];
        #pragma unroll
        for (int i = 0; i < 16; ++i) occ[i] = 0.f;
        #pragma unroll 4
        for (int o = 0; o < 64; ++o) {
            float a0 = Ss[(r0+0)*65+o], a1 = Ss[(r0+1)*65+o];
            float a2 = Ss[(r0+2)*65+o], a3 = Ss[(r0+3)*65+o];
            float b0 = Ws[(c0+0)*65+o], b1 = Ws[(c0+1)*65+o];
            float b2 = Ws[(c0+2)*65+o], b3 = Ws[(c0+3)*65+o];
            occ[0]  += a0*b0; occ[1]  += a0*b1; occ[2]  += a0*b2; occ[3]  += a0*b3;
            occ[4]  += a1*b0; occ[5]  += a1*b1; occ[6]  += a1*b2; occ[7]  += a1*b3;
            occ[8]  += a2*b0; occ[9]  += a2*b1; occ[10] += a2*b2; occ[11] += a2*b3;
            occ[12] += a3*b0; occ[13] += a3*b1; occ[14] += a3*b2; occ[15] += a3*b3;
        }
        #pragma unroll
        for (int i = 0; i < 4; ++i) {
            float wq = WG[(0 * 64 + r0 + i) * 16 + p];
            float wk = WG[(1 * 64 + r0 + i) * 16 + p];
            float wv = WG[(2 * 64 + r0 + i) * 16 + p];
            #pragma unroll
            for (int j = 0; j < 4; ++j) {
                aq[i * 4 + j] += wq * occ[i * 4 + j];
                ak[i * 4 + j] += wk * occ[i * 4 + j];
                av[i * 4 + j] += wv * occ[i * 4 + j];
            }
        }
    }
    #pragma unroll
    for (int i = 0; i < 4; ++i)
        #pragma unroll
        for (int j = 0; j < 4; ++j) {
            size_t idx = (size_t)(row0 + r0 + i) * 64 + c0 + j;
            g_q[idx] = aq[i * 4 + j];
            g_k[idx] = ak[i * 4 + j];
            g_v[idx] = av[i * 4 + j];
        }
}

// ---------------- K3: causal flash attention (fp32) ----------------
__global__ __launch_bounds__(256, 2) void k_attn() {
    extern __shared__ float sm[];
    float* Qs = sm;
    float* Ks = sm + 64 * 65;
    float* Vs = sm + 2 * 64 * 65;
    float* Ps = sm + 3 * 64 * 65;
    const int tid = threadIdx.x;
    const int qt = blockIdx.x, bh = blockIdx.y;
    const int b = bh >> 3, h = bh & 7;
    const int ty = tid >> 4, tx = tid & 15;
    const int r0 = ty * 4, c0 = tx * 4;

    for (int i = tid; i < 4096; i += 256) {
        int r = i >> 6, d = i & 63;
        Qs[r * 65 + d] = g_q[((size_t)(b * NT + qt * 64 + r) * NHEAD + h) * 64 + d];
    }
    float m[4], l[4], O[16];
    #pragma unroll
    for (int i = 0; i < 4; ++i) { m[i] = -1e30f; l[i] = 0.f; }
    #pragma unroll
    for (int i = 0; i < 16; ++i) O[i] = 0.f;

    for (int kt = 0; kt <= qt; ++kt) {
        __syncthreads();
        for (int i = tid; i < 4096; i += 256) {
            int r = i >> 6, d = i & 63;
            size_t base = ((size_t)(b * NT + kt * 64 + r) * NHEAD + h) * 64 + d;
            Ks[r * 65 + d] = g_k[base];
            Vs[r * 65 + d] = g_v[base];
        }
        __syncthreads();

        float s[16];
        #pragma unroll
        for (int i = 0; i < 16; ++i) s[i] = 0.f;
        #pragma unroll 4
        for (int d = 0; d < 64; ++d) {
            float a0 = Qs[(r0+0)*65+d], a1 = Qs[(r0+1)*65+d];
            float a2 = Qs[(r0+2)*65+d], a3 = Qs[(r0+3)*65+d];
            float b0 = Ks[(c0+0)*65+d], b1 = Ks[(c0+1)*65+d];
            float b2 = Ks[(c0+2)*65+d], b3 = Ks[(c0+3)*65+d];
            s[0]  += a0*b0; s[1]  += a0*b1; s[2]  += a0*b2; s[3]  += a0*b3;
            s[4]  += a1*b0; s[5]  += a1*b1; s[6]  += a1*b2; s[7]  += a1*b3;
            s[8]  += a2*b0; s[9]  += a2*b1; s[10] += a2*b2; s[11] += a2*b3;
            s[12] += a3*b0; s[13] += a3*b1; s[14] += a3*b2; s[15] += a3*b3;
        }
        const bool diag = (kt == qt);
        #pragma unroll
        for (int i = 0; i < 4; ++i)
            #pragma unroll
            for (int j = 0; j < 4; ++j) {
                float v = s[i * 4 + j] * 0.125f;
                if (diag && (c0 + j > r0 + i)) v = -1e30f;
                s[i * 4 + j] = v;
            }
        #pragma unroll
        for (int i = 0; i < 4; ++i) {
            float mi = fmaxf(fmaxf(s[i*4], s[i*4+1]), fmaxf(s[i*4+2], s[i*4+3]));
            #pragma unroll
            for (int o = 8; o; o >>= 1)
                mi = fmaxf(mi, __shfl_xor_sync(0xffffffffu, mi, o));
            float mn = fmaxf(m[i], mi);
            float alpha = __expf(m[i] - mn);
            m[i] = mn;
            float rs = 0.f;
            #pragma unroll
            for (int j = 0; j < 4; ++j) {
                float pv = __expf(s[i * 4 + j] - mn);
                s[i * 4 + j] = pv;
                rs += pv;
            }
            #pragma unroll
            for (int o = 8; o; o >>= 1)
                rs += __shfl_xor_sync(0xffffffffu, rs, o);
            l[i] = l[i] * alpha + rs;
            #pragma unroll
            for (int j = 0; j < 4; ++j) {
                O[i * 4 + j] *= alpha;
                Ps[(r0 + i) * 65 + (c0 + j)] = s[i * 4 + j];
            }
        }
        __syncthreads();
        #pragma unroll 4
        for (int o = 0; o < 64; ++o) {
            float a0 = Ps[(r0+0)*65+o], a1 = Ps[(r0+1)*65+o];
            float a2 = Ps[(r0+2)*65+o], a3 = Ps[(r0+3)*65+o];
            float b0 = Vs[o*65+c0+0], b1 = Vs[o*65+c0+1];
            float b2 = Vs[o*65+c0+2], b3 = Vs[o*65+c0+3];
            O[0]  += a0*b0; O[1]  += a0*b1; O[2]  += a0*b2; O[3]  += a0*b3;
            O[4]  += a1*b0; O[5]  += a1*b1; O[6]  += a1*b2; O[7]  += a1*b3;
            O[8]  += a2*b0; O[9]  += a2*b1; O[10] += a2*b2; O[11] += a2*b3;
            O[12] += a3*b0; O[13] += a3*b1; O[14] += a3*b2; O[15] += a3*b3;
        }
    }
    #pragma unroll
    for (int i = 0; i < 4; ++i) {
        float invl = 1.f / l[i];
        #pragma unroll
        for (int j = 0; j < 4; ++j)
            g_attn[((size_t)(b * NT + qt * 64 + r0 + i) * NHEAD + h) * 64 + c0 + j]
                = O[i * 4 + j] * invl;
    }
}

// ---------------- K4: logits = x@head_w^T + attn@C ----------------
__global__ __launch_bounds__(128) void k_final(const float* __restrict__ head_w,
                                               float* __restrict__ out) {
    int t = blockIdx.x;                 // token
    int tid = threadIdx.x;
    int v = tid & 15, ch = tid >> 4;    // 8 chunks of 64
    const float* xr = g_x + (size_t)t * DMODEL;
    const float* ar = g_attn + (size_t)t * DMODEL;
    float acc = 0.f;
    int d0 = ch * 64;
    #pragma unroll 8
    for (int d = d0; d < d0 + 64; ++d)
        acc += xr[d] * head_w[v * DMODEL + d] + ar[d] * g_C[d * NVOC + v];
    __shared__ float red[128];
    red[tid] = acc;
    __syncthreads();
    if (ch == 0) {
        float s = 0.f;
        #pragma unroll
        for (int c = 0; c < 8; ++c) s += red[c * 16 + v];
        out[(size_t)t * NVOC + v] = s;
    }
}

// ---------------- launch ----------------
extern "C" void kernel_launch(void* const* d_in, const int* in_sizes, int n_in,
                              void* d_out, int out_size) {
    const int*   ids    = (const int*)d_in[0];
    const float* embed  = (const float*)d_in[1];
    const float* ln_g   = (const float*)d_in[2];
    const float* ln_b   = (const float*)d_in[3];
    const float* pq     = (const float*)d_in[4];
    const float* gq     = (const float*)d_in[5];
    const float* pk     = (const float*)d_in[6];
    const float* gk     = (const float*)d_in[7];
    const float* pv     = (const float*)d_in[8];
    const float* gv     = (const float*)d_in[9];
    const float* w1     = (const float*)d_in[10];
    const float* w2     = (const float*)d_in[11];
    const float* o_w    = (const float*)d_in[12];
    const float* head_w = (const float*)d_in[13];
    float* out = (float*)d_out;

    static_assert(3 * 64 * 65 + 3 * 64 * 16 == 15552, "smem layout");
    const int smem_compose = (3 * 64 * 65 + 3 * 64 * 16) * 4;  // 62208 B
    const int smem_attn    = 4 * 64 * 65 * 4;                   // 66560 B
    cudaFuncSetAttribute(k_compose, cudaFuncAttributeMaxDynamicSharedMemorySize, smem_compose);
    cudaFuncSetAttribute(k_attn,    cudaFuncAttributeMaxDynamicSharedMemorySize, smem_attn);

    k_compute_C<<<32, 256>>>(o_w, head_w);
    k_embed_ln<<<NTOK, 128>>>(ids, embed, ln_g, ln_b);
    k_compose<<<NTH / 64, 256, smem_compose>>>(pq, gq, pk, gk, pv, gv, w1, w2);
    dim3 ag(NT / 64, NB * NHEAD);
    k_attn<<<ag, 256, smem_attn>>>();
    k_final<<<NTOK, 128>>>(head_w, out);
}

// round 3
// speedup vs baseline: 1.2312x; 1.2312x over previous
#include <cuda_runtime.h>

#define NHEAD 8
#define HD 64
#define DMODEL 512
#define NP 16
#define NB 2
#define NT 2048
#define NVOC 16
#define NTOK (NB*NT)        // 4096
#define NTH (NTOK*NHEAD)    // 32768

// ---------------- scratch ----------------
__device__ float g_x[NTOK*DMODEL];
__device__ float g_h[NTOK*DMODEL];
__device__ float g_q[NTH*HD];     // layout [bh][t][64]
__device__ float g_k[NTH*HD];
__device__ float g_v[NTH*HD];
__device__ float g_attn[NTH*HD];  // layout [token][head][64]
__device__ float g_C[DMODEL*NVOC];

__device__ __forceinline__ unsigned to_tf32(float x) {
    unsigned u;
    asm("cvt.rna.tf32.f32 %0, %1;" : "=r"(u) : "f"(x));
    return u;
}

__device__ __forceinline__ void mma_u(float* c, const unsigned* a, const unsigned* b) {
    asm volatile(
        "mma.sync.aligned.m16n8k8.row.col.f32.tf32.tf32.f32 "
        "{%0,%1,%2,%3}, {%4,%5,%6,%7}, {%8,%9}, {%0,%1,%2,%3};\n"
        : "+f"(c[0]), "+f"(c[1]), "+f"(c[2]), "+f"(c[3])
        : "r"(a[0]), "r"(a[1]), "r"(a[2]), "r"(a[3]),
          "r"(b[0]), "r"(b[1]));
}

// 3xTF32: c += a*b with ~fp32 precision.
// Split a=ah+al, b=bh+bl (tf32-rounded); accumulate al*bh + ah*bl + ah*bh.
struct SplitA { unsigned h[4], l[4]; };
struct SplitB { unsigned h[2], l[2]; };

__device__ __forceinline__ SplitA split_a(const float* a) {
    SplitA s;
    #pragma unroll
    for (int i = 0; i < 4; ++i) {
        s.h[i] = to_tf32(a[i]);
        s.l[i] = to_tf32(a[i] - __uint_as_float(s.h[i]));
    }
    return s;
}
__device__ __forceinline__ SplitB split_b(const float* b) {
    SplitB s;
    #pragma unroll
    for (int i = 0; i < 2; ++i) {
        s.h[i] = to_tf32(b[i]);
        s.l[i] = to_tf32(b[i] - __uint_as_float(s.h[i]));
    }
    return s;
}
__device__ __forceinline__ void mma3(float* c, const SplitA& a, const SplitB& b) {
    mma_u(c, a.l, b.h);
    mma_u(c, a.h, b.l);
    mma_u(c, a.h, b.h);
}

__device__ __forceinline__ float fast_exp2(float x) {
    float r;
    asm("ex2.approx.f32 %0, %1;" : "=f"(r) : "f"(x));
    return r;
}

// ---------------- K0: C[d][v] = sum_e o_w[e,d]*head_w[v,e] ----------------
__global__ void k_compute_C(const float* __restrict__ o_w,
                            const float* __restrict__ head_w) {
    int idx = blockIdx.x * blockDim.x + threadIdx.x;
    if (idx >= DMODEL * NVOC) return;
    int d = idx >> 4, v = idx & 15;
    float acc = 0.f;
    #pragma unroll 8
    for (int e = 0; e < DMODEL; ++e)
        acc += o_w[e * DMODEL + d] * head_w[v * DMODEL + e];
    g_C[d * NVOC + v] = acc;
}

// ---------------- K1: embedding + layernorm ----------------
__global__ __launch_bounds__(128) void k_embed_ln(
    const int* __restrict__ ids, const float* __restrict__ embed,
    const float* __restrict__ lng, const float* __restrict__ lnb) {
    int t = blockIdx.x;
    int tid = threadIdx.x;
    const float4* row = (const float4*)(embed + (size_t)ids[t] * DMODEL);
    float4 xv = row[tid];
    float s  = xv.x + xv.y + xv.z + xv.w;
    float s2 = xv.x*xv.x + xv.y*xv.y + xv.z*xv.z + xv.w*xv.w;
    #pragma unroll
    for (int o = 16; o; o >>= 1) {
        s  += __shfl_xor_sync(0xffffffffu, s, o);
        s2 += __shfl_xor_sync(0xffffffffu, s2, o);
    }
    __shared__ float sh[8];
    int w = tid >> 5;
    if ((tid & 31) == 0) { sh[w] = s; sh[4 + w] = s2; }
    __syncthreads();
    s  = sh[0] + sh[1] + sh[2] + sh[3];
    s2 = sh[4] + sh[5] + sh[6] + sh[7];
    float mu  = s * (1.0f / DMODEL);
    float var = s2 * (1.0f / DMODEL) - mu * mu;
    float inv = rsqrtf(var + 1e-5f);
    float4 gv = ((const float4*)lng)[tid];
    float4 bv = ((const float4*)lnb)[tid];
    float4 hv;
    hv.x = (xv.x - mu) * inv * gv.x + bv.x;
    hv.y = (xv.y - mu) * inv * gv.y + bv.y;
    hv.z = (xv.z - mu) * inv * gv.z + bv.z;
    hv.w = (xv.w - mu) * inv * gv.w + bv.w;
    ((float4*)(g_x + (size_t)t * DMODEL))[tid] = xv;
    ((float4*)(g_h + (size_t)t * DMODEL))[tid] = hv;
}

// ---------------- K2: compose via 3xTF32 mma ----------------
// 512 threads = 16 warps laid out 8(rows)x2(n-halves). M=128 rows/block.
#define XS_STR 68
__global__ __launch_bounds__(512, 1) void k_compose(
    const float* __restrict__ pq, const float* __restrict__ gq,
    const float* __restrict__ pk, const float* __restrict__ gk,
    const float* __restrict__ pv, const float* __restrict__ gv,
    const float* __restrict__ w1, const float* __restrict__ w2) {
    extern __shared__ float sm[];
    float* Xs  = sm;                    // 128 x 68
    float* W1s = Xs + 128 * XS_STR;     // 64 x 68
    float* W2s = W1s + 64 * XS_STR;     // 64 x 68
    float* Ss  = W2s + 64 * XS_STR;     // 128 x 68
    float* WG  = Ss + 128 * XS_STR;     // 3 x 128 x 16

    const int tid = threadIdx.x, warp = tid >> 5, lane = tid & 31;
    const int g = lane >> 2, tg = lane & 3;
    const int wy = warp >> 1, wx = warp & 1;
    const int wr0 = wy * 16, nc0 = wx * 32;
    const int row0 = blockIdx.x * 128;

    for (int i = tid; i < 128 * 16; i += 512) {
        int r = i >> 4, c = i & 15;
        *(float4*)&Xs[r * XS_STR + c * 4] =
            ((const float4*)(g_h + (size_t)(row0 + r) * 64))[c];
    }
    __syncthreads();

    for (int i = tid; i < 128 * 16; i += 512) {
        int r = i >> 4, p = i & 15;
        float dq = 0.f, dk = 0.f, dv = 0.f;
        #pragma unroll 8
        for (int d = 0; d < 64; ++d) {
            float xv = Xs[r * XS_STR + d];
            dq += xv * pq[p * 64 + d];
            dk += xv * pk[p * 64 + d];
            dv += xv * pv[p * 64 + d];
        }
        float lq = dq * 0.125f - gq[p];
        float lk = dk * 0.125f - gk[p];
        float lv = dv * 0.125f - gv[p];
        WG[(0 * 128 + r) * 16 + p] = lq > 1e-6f ? lq : 0.f;
        WG[(1 * 128 + r) * 16 + p] = lk > 1e-6f ? lk : 0.f;
        WG[(2 * 128 + r) * 16 + p] = lv > 1e-6f ? lv : 0.f;
    }

    float aq[16], ak[16], av[16];
    #pragma unroll
    for (int i = 0; i < 16; ++i) { aq[i] = 0.f; ak[i] = 0.f; av[i] = 0.f; }

    const float LOG2E = 1.44269504f;

    for (int p = 0; p < NP; ++p) {
        __syncthreads();
        for (int i = tid; i < 64 * 16; i += 512) {
            int r = i >> 4, c = i & 15;
            *(float4*)&W1s[r * XS_STR + c * 4] =
                ((const float4*)(w1 + (size_t)p * 4096 + r * 64))[c];
            *(float4*)&W2s[r * XS_STR + c * 4] =
                ((const float4*)(w2 + (size_t)p * 4096 + r * 64))[c];
        }
        __syncthreads();

        // GEMM1: H = X @ W1^T  (warp: 16 rows x 32 cols)
        float hb[16];
        #pragma unroll
        for (int i = 0; i < 16; ++i) hb[i] = 0.f;
        #pragma unroll
        for (int ks = 0; ks < 8; ++ks) {
            int k0 = ks * 8;
            float a[4];
            a[0] = Xs[(wr0 + g)     * XS_STR + k0 + tg];
            a[1] = Xs[(wr0 + g + 8) * XS_STR + k0 + tg];
            a[2] = Xs[(wr0 + g)     * XS_STR + k0 + tg + 4];
            a[3] = Xs[(wr0 + g + 8) * XS_STR + k0 + tg + 4];
            SplitA sa = split_a(a);
            #pragma unroll
            for (int nt = 0; nt < 4; ++nt) {
                float b[2];
                b[0] = W1s[(nc0 + nt * 8 + g) * XS_STR + k0 + tg];
                b[1] = W1s[(nc0 + nt * 8 + g) * XS_STR + k0 + tg + 4];
                SplitB sb = split_b(b);
                mma3(&hb[nt * 4], sa, sb);
            }
        }
        // silu, write to Ss
        #pragma unroll
        for (int nt = 0; nt < 4; ++nt) {
            #pragma unroll
            for (int j = 0; j < 4; ++j) {
                float h = hb[nt * 4 + j];
                hb[nt * 4 + j] = h / (1.f + fast_exp2(-h * LOG2E));
            }
            *(float2*)&Ss[(wr0 + g)     * XS_STR + nc0 + nt * 8 + 2 * tg] =
                make_float2(hb[nt * 4 + 0], hb[nt * 4 + 1]);
            *(float2*)&Ss[(wr0 + g + 8) * XS_STR + nc0 + nt * 8 + 2 * tg] =
                make_float2(hb[nt * 4 + 2], hb[nt * 4 + 3]);
        }
        __syncthreads();

        // GEMM2: out = silu(H) @ W2^T
        float ob[16];
        #pragma unroll
        for (int i = 0; i < 16; ++i) ob[i] = 0.f;
        #pragma unroll
        for (int ks = 0; ks < 8; ++ks) {
            int k0 = ks * 8;
            float a[4];
            a[0] = Ss[(wr0 + g)     * XS_STR + k0 + tg];
            a[1] = Ss[(wr0 + g + 8) * XS_STR + k0 + tg];
            a[2] = Ss[(wr0 + g)     * XS_STR + k0 + tg + 4];
            a[3] = Ss[(wr0 + g + 8) * XS_STR + k0 + tg + 4];
            SplitA sa = split_a(a);
            #pragma unroll
            for (int nt = 0; nt < 4; ++nt) {
                float b[2];
                b[0] = W2s[(nc0 + nt * 8 + g) * XS_STR + k0 + tg];
                b[1] = W2s[(nc0 + nt * 8 + g) * XS_STR + k0 + tg + 4];
                SplitB sb = split_b(b);
                mma3(&ob[nt * 4], sa, sb);
            }
        }
        // gated accumulate
        float wq0 = WG[(0 * 128 + wr0 + g)     * 16 + p];
        float wq1 = WG[(0 * 128 + wr0 + g + 8) * 16 + p];
        float wk0 = WG[(1 * 128 + wr0 + g)     * 16 + p];
        float wk1 = WG[(1 * 128 + wr0 + g + 8) * 16 + p];
        float wv0 = WG[(2 * 128 + wr0 + g)     * 16 + p];
        float wv1 = WG[(2 * 128 + wr0 + g + 8) * 16 + p];
        #pragma unroll
        for (int nt = 0; nt < 4; ++nt) {
            aq[nt*4+0] += wq0 * ob[nt*4+0]; aq[nt*4+1] += wq0 * ob[nt*4+1];
            aq[nt*4+2] += wq1 * ob[nt*4+2]; aq[nt*4+3] += wq1 * ob[nt*4+3];
            ak[nt*4+0] += wk0 * ob[nt*4+0]; ak[nt*4+1] += wk0 * ob[nt*4+1];
            ak[nt*4+2] += wk1 * ob[nt*4+2]; ak[nt*4+3] += wk1 * ob[nt*4+3];
            av[nt*4+0] += wv0 * ob[nt*4+0]; av[nt*4+1] += wv0 * ob[nt*4+1];
            av[nt*4+2] += wv1 * ob[nt*4+2]; av[nt*4+3] += wv1 * ob[nt*4+3];
        }
    }

    // write q,k,v to [bh][t][64]
    int r_lo = row0 + wr0 + g;
    int r_hi = r_lo + 8;
    int tok_lo = r_lo >> 3, h_lo = r_lo & 7;
    int tok_hi = r_hi >> 3, h_hi = r_hi & 7;
    int b_lo = tok_lo >> 11, t_lo = tok_lo & 2047;
    int b_hi = tok_hi >> 11, t_hi = tok_hi & 2047;
    size_t base_lo = ((size_t)(b_lo * 8 + h_lo) * NT + t_lo) * 64;
    size_t base_hi = ((size_t)(b_hi * 8 + h_hi) * NT + t_hi) * 64;
    #pragma unroll
    for (int nt = 0; nt < 4; ++nt) {
        int col = nc0 + nt * 8 + 2 * tg;
        *(float2*)&g_q[base_lo + col] = make_float2(aq[nt*4+0], aq[nt*4+1]);
        *(float2*)&g_q[base_hi + col] = make_float2(aq[nt*4+2], aq[nt*4+3]);
        *(float2*)&g_k[base_lo + col] = make_float2(ak[nt*4+0], ak[nt*4+1]);
        *(float2*)&g_k[base_hi + col] = make_float2(ak[nt*4+2], ak[nt*4+3]);
        *(float2*)&g_v[base_lo + col] = make_float2(av[nt*4+0], av[nt*4+1]);
        *(float2*)&g_v[base_hi + col] = make_float2(av[nt*4+2], av[nt*4+3]);
    }
}

// ---------------- K3: flash attention via 3xTF32 mma ----------------
// 256 threads = 8 warps x 16 q rows; 128-row Q tile, 64-row K tile.
#define VS_STR 72
__global__ __launch_bounds__(256, 2) void k_attn() {
    extern __shared__ float sm[];
    float* Qs = sm;                    // 128 x 68
    float* Ks = Qs + 128 * XS_STR;     // 64 x 68
    float* Vs = Ks + 64 * XS_STR;      // 64 x 72
    float* Ps = Vs + 64 * VS_STR;      // 128 x 68

    const int tid = threadIdx.x, warp = tid >> 5, lane = tid & 31;
    const int g = lane >> 2, tg = lane & 3;
    const int qtile = gridDim.x - 1 - blockIdx.x;
    const int qt0 = qtile * 128;
    const int bh = blockIdx.y;
    const int b = bh >> 3, h = bh & 7;
    const float* qbase = g_q + (size_t)bh * NT * 64;
    const float* kbase = g_k + (size_t)bh * NT * 64;
    const float* vbase = g_v + (size_t)bh * NT * 64;
    const int wr0 = warp * 16;

    for (int i = tid; i < 128 * 16; i += 256) {
        int r = i >> 4, c = i & 15;
        *(float4*)&Qs[r * XS_STR + c * 4] =
            ((const float4*)(qbase + (size_t)(qt0 + r) * 64))[c];
    }

    float O[32];
    #pragma unroll
    for (int i = 0; i < 32; ++i) O[i] = 0.f;
    float m2[2] = {-1e30f, -1e30f};
    float l[2] = {0.f, 0.f};
    const float sc = 0.125f * 1.44269504f;

    const int ktmax = (qt0 >> 6) + 1;
    for (int kt = 0; kt <= ktmax; ++kt) {
        __syncthreads();
        for (int i = tid; i < 64 * 16; i += 256) {
            int r = i >> 4, c = i & 15;
            *(float4*)&Ks[r * XS_STR + c * 4] =
                ((const float4*)(kbase + (size_t)(kt * 64 + r) * 64))[c];
            *(float4*)&Vs[r * VS_STR + c * 4] =
                ((const float4*)(vbase + (size_t)(kt * 64 + r) * 64))[c];
        }
        __syncthreads();

        // S = Q K^T
        float s[32];
        #pragma unroll
        for (int i = 0; i < 32; ++i) s[i] = 0.f;
        #pragma unroll
        for (int ks = 0; ks < 8; ++ks) {
            int k0 = ks * 8;
            float a[4];
            a[0] = Qs[(wr0 + g)     * XS_STR + k0 + tg];
            a[1] = Qs[(wr0 + g + 8) * XS_STR + k0 + tg];
            a[2] = Qs[(wr0 + g)     * XS_STR + k0 + tg + 4];
            a[3] = Qs[(wr0 + g + 8) * XS_STR + k0 + tg + 4];
            SplitA sa = split_a(a);
            #pragma unroll
            for (int nt = 0; nt < 8; ++nt) {
                float bfr[2];
                bfr[0] = Ks[(nt * 8 + g) * XS_STR + k0 + tg];
                bfr[1] = Ks[(nt * 8 + g) * XS_STR + k0 + tg + 4];
                SplitB sb = split_b(bfr);
                mma3(&s[nt * 4], sa, sb);
            }
        }
        // scale to base-2 + causal mask
        const bool maskt = (kt * 64 + 63 > qt0 + wr0);
        #pragma unroll
        for (int nt = 0; nt < 8; ++nt)
            #pragma unroll
            for (int j = 0; j < 4; ++j) {
                int rr = qt0 + wr0 + g + (j >> 1) * 8;
                int cc = kt * 64 + nt * 8 + 2 * tg + (j & 1);
                float v = s[nt * 4 + j] * sc;
                if (maskt && cc > rr) v = -1e30f;
                s[nt * 4 + j] = v;
            }
        // online softmax
        #pragma unroll
        for (int h2 = 0; h2 < 2; ++h2) {
            float mx = -1e30f;
            #pragma unroll
            for (int nt = 0; nt < 8; ++nt) {
                mx = fmaxf(mx, s[nt * 4 + h2 * 2 + 0]);
                mx = fmaxf(mx, s[nt * 4 + h2 * 2 + 1]);
            }
            mx = fmaxf(mx, __shfl_xor_sync(0xffffffffu, mx, 1));
            mx = fmaxf(mx, __shfl_xor_sync(0xffffffffu, mx, 2));
            float mn = fmaxf(m2[h2], mx);
            float alpha = fast_exp2(m2[h2] - mn);
            m2[h2] = mn;
            float rs = 0.f;
            #pragma unroll
            for (int nt = 0; nt < 8; ++nt) {
                float p0 = fast_exp2(s[nt * 4 + h2 * 2 + 0] - mn);
                float p1 = fast_exp2(s[nt * 4 + h2 * 2 + 1] - mn);
                s[nt * 4 + h2 * 2 + 0] = p0;
                s[nt * 4 + h2 * 2 + 1] = p1;
                rs += p0 + p1;
            }
            rs += __shfl_xor_sync(0xffffffffu, rs, 1);
            rs += __shfl_xor_sync(0xffffffffu, rs, 2);
            l[h2] = l[h2] * alpha + rs;
            #pragma unroll
            for (int nt = 0; nt < 8; ++nt) {
                O[nt * 4 + h2 * 2 + 0] *= alpha;
                O[nt * 4 + h2 * 2 + 1] *= alpha;
            }
        }
        // P -> smem (warp-private rows)
        #pragma unroll
        for (int nt = 0; nt < 8; ++nt) {
            *(float2*)&Ps[(wr0 + g)     * XS_STR + nt * 8 + 2 * tg] =
                make_float2(s[nt * 4 + 0], s[nt * 4 + 1]);
            *(float2*)&Ps[(wr0 + g + 8) * XS_STR + nt * 8 + 2 * tg] =
                make_float2(s[nt * 4 + 2], s[nt * 4 + 3]);
        }
        __syncwarp();
        // O += P V
        #pragma unroll
        for (int ks = 0; ks < 8; ++ks) {
            int k0 = ks * 8;
            float a[4];
            a[0] = Ps[(wr0 + g)     * XS_STR + k0 + tg];
            a[1] = Ps[(wr0 + g + 8) * XS_STR + k0 + tg];
            a[2] = Ps[(wr0 + g)     * XS_STR + k0 + tg + 4];
            a[3] = Ps[(wr0 + g + 8) * XS_STR + k0 + tg + 4];
            SplitA sa = split_a(a);
            #pragma unroll
            for (int nt = 0; nt < 8; ++nt) {
                float bfr[2];
                bfr[0] = Vs[(k0 + tg)     * VS_STR + nt * 8 + g];
                bfr[1] = Vs[(k0 + tg + 4) * VS_STR + nt * 8 + g];
                SplitB sb = split_b(bfr);
                mma3(&O[nt * 4], sa, sb);
            }
        }
    }

    float inv0 = 1.f / l[0];
    float inv1 = 1.f / l[1];
    int r_lo = qt0 + wr0 + g;
    int r_hi = r_lo + 8;
    size_t base_lo = ((size_t)(b * NT + r_lo) * 8 + h) * 64;
    size_t base_hi = ((size_t)(b * NT + r_hi) * 8 + h) * 64;
    #pragma unroll
    for (int nt = 0; nt < 8; ++nt) {
        int col = nt * 8 + 2 * tg;
        *(float2*)&g_attn[base_lo + col] =
            make_float2(O[nt*4+0] * inv0, O[nt*4+1] * inv0);
        *(float2*)&g_attn[base_hi + col] =
            make_float2(O[nt*4+2] * inv1, O[nt*4+3] * inv1);
    }
}

// ---------------- K4: logits = x@head_w^T + attn@C ----------------
__global__ __launch_bounds__(128) void k_final(const float* __restrict__ head_w,
                                               float* __restrict__ out) {
    int t = blockIdx.x;
    int tid = threadIdx.x;
    int v = tid & 15, ch = tid >> 4;
    const float* xr = g_x + (size_t)t * DMODEL;
    const float* ar = g_attn + (size_t)t * DMODEL;
    float acc = 0.f;
    int d0 = ch * 64;
    #pragma unroll 8
    for (int d = d0; d < d0 + 64; ++d)
        acc += xr[d] * head_w[v * DMODEL + d] + ar[d] * g_C[d * NVOC + v];
    __shared__ float red[128];
    red[tid] = acc;
    __syncthreads();
    if (ch == 0) {
        float s = 0.f;
        #pragma unroll
        for (int c = 0; c < 8; ++c) s += red[c * 16 + v];
        out[(size_t)t * NVOC + v] = s;
    }
}

// ---------------- launch ----------------
extern "C" void kernel_launch(void* const* d_in, const int* in_sizes, int n_in,
                              void* d_out, int out_size) {
    const int*   ids    = (const int*)d_in[0];
    const float* embed  = (const float*)d_in[1];
    const float* ln_g   = (const float*)d_in[2];
    const float* ln_b   = (const float*)d_in[3];
    const float* pq     = (const float*)d_in[4];
    const float* gq     = (const float*)d_in[5];
    const float* pk     = (const float*)d_in[6];
    const float* gk     = (const float*)d_in[7];
    const float* pv     = (const float*)d_in[8];
    const float* gv     = (const float*)d_in[9];
    const float* w1     = (const float*)d_in[10];
    const float* w2     = (const float*)d_in[11];
    const float* o_w    = (const float*)d_in[12];
    const float* head_w = (const float*)d_in[13];
    float* out = (float*)d_out;

    const int smem_compose = (128*XS_STR + 2*64*XS_STR + 128*XS_STR + 3*128*16) * 4;
    const int smem_attn    = (128*XS_STR + 64*XS_STR + 64*VS_STR + 128*XS_STR) * 4;
    cudaFuncSetAttribute(k_compose, cudaFuncAttributeMaxDynamicSharedMemorySize, smem_compose);
    cudaFuncSetAttribute(k_attn,    cudaFuncAttributeMaxDynamicSharedMemorySize, smem_attn);

    k_compute_C<<<32, 256>>>(o_w, head_w);
    k_embed_ln<<<NTOK, 128>>>(ids, embed, ln_g, ln_b);
    k_compose<<<NTH / 128, 512, smem_compose>>>(pq, gq, pk, gk, pv, gv, w1, w2);
    dim3 ag(NT / 128, NB * NHEAD);
    k_attn<<<ag, 256, smem_attn>>>();
    k_final<<<NTOK, 128>>>(head_w, out);
}

// round 4
// speedup vs baseline: 1.9431x; 1.5782x over previous
#include <cuda_runtime.h>

#define NHEAD 8
#define HD 64
#define DMODEL 512
#define NP 16
#define NB 2
#define NT 2048
#define NVOC 16
#define NTOK (NB*NT)        // 4096
#define NTH (NTOK*NHEAD)    // 32768

#define STR 72    // bf16 halfs per smem plane row
#define WSTR 36   // 32-bit words per row

// ---------------- scratch ----------------
__device__ float g_x[NTOK*DMODEL];
__device__ float g_h[NTOK*DMODEL];
__device__ float g_q[NTH*HD];     // [bh][t][64]
__device__ float g_k[NTH*HD];
__device__ float g_v[NTH*HD];
__device__ float g_attn[NTH*HD];  // [token][head][64]
__device__ float g_C[DMODEL*NVOC];

// pack (x0,x1) -> bf16x2 hi word + bf16x2 residual word (x0 in low half)
__device__ __forceinline__ void split2(float x0, float x1, unsigned &h, unsigned &l) {
    asm("cvt.rn.bf16x2.f32 %0, %1, %2;" : "=r"(h) : "f"(x1), "f"(x0));
    float h0 = __uint_as_float(h << 16);
    float h1 = __uint_as_float(h & 0xffff0000u);
    asm("cvt.rn.bf16x2.f32 %0, %1, %2;" : "=r"(l) : "f"(x1 - h1), "f"(x0 - h0));
}

__device__ __forceinline__ void mma_bf16(float* c, unsigned a0, unsigned a1,
                                         unsigned a2, unsigned a3,
                                         unsigned b0, unsigned b1) {
    asm volatile(
        "mma.sync.aligned.m16n8k16.row.col.f32.bf16.bf16.f32 "
        "{%0,%1,%2,%3}, {%4,%5,%6,%7}, {%8,%9}, {%0,%1,%2,%3};\n"
        : "+f"(c[0]), "+f"(c[1]), "+f"(c[2]), "+f"(c[3])
        : "r"(a0), "r"(a1), "r"(a2), "r"(a3), "r"(b0), "r"(b1));
}

// c += (Ah+Al)*(Bh+Bl) dropping Al*Bl
__device__ __forceinline__ void mma3(float* c, const unsigned* ah, const unsigned* al,
                                     unsigned b0h, unsigned b1h,
                                     unsigned b0l, unsigned b1l) {
    mma_bf16(c, al[0], al[1], al[2], al[3], b0h, b1h);
    mma_bf16(c, ah[0], ah[1], ah[2], ah[3], b0l, b1l);
    mma_bf16(c, ah[0], ah[1], ah[2], ah[3], b0h, b1h);
}

__device__ __forceinline__ void ldm_x4(unsigned* r, const unsigned short* p) {
    unsigned a = (unsigned)__cvta_generic_to_shared(p);
    asm volatile("ldmatrix.sync.aligned.m8n8.x4.shared.b16 {%0,%1,%2,%3}, [%4];"
                 : "=r"(r[0]), "=r"(r[1]), "=r"(r[2]), "=r"(r[3]) : "r"(a));
}
__device__ __forceinline__ void ldm_x4_t(unsigned* r, const unsigned short* p) {
    unsigned a = (unsigned)__cvta_generic_to_shared(p);
    asm volatile("ldmatrix.sync.aligned.m8n8.x4.trans.shared.b16 {%0,%1,%2,%3}, [%4];"
                 : "=r"(r[0]), "=r"(r[1]), "=r"(r[2]), "=r"(r[3]) : "r"(a));
}

__device__ __forceinline__ float fast_exp2(float x) {
    float r;
    asm("ex2.approx.f32 %0, %1;" : "=f"(r) : "f"(x));
    return r;
}

// ---------------- K0: C[d][v] = sum_e o_w[e,d]*head_w[v,e] ----------------
__global__ void k_compute_C(const float* __restrict__ o_w,
                            const float* __restrict__ head_w) {
    int idx = blockIdx.x * blockDim.x + threadIdx.x;
    if (idx >= DMODEL * NVOC) return;
    int d = idx >> 4, v = idx & 15;
    float acc = 0.f;
    #pragma unroll 8
    for (int e = 0; e < DMODEL; ++e)
        acc += o_w[e * DMODEL + d] * head_w[v * DMODEL + e];
    g_C[d * NVOC + v] = acc;
}

// ---------------- K1: embedding + layernorm ----------------
__global__ __launch_bounds__(128) void k_embed_ln(
    const int* __restrict__ ids, const float* __restrict__ embed,
    const float* __restrict__ lng, const float* __restrict__ lnb) {
    int t = blockIdx.x;
    int tid = threadIdx.x;
    const float4* row = (const float4*)(embed + (size_t)ids[t] * DMODEL);
    float4 xv = row[tid];
    float s  = xv.x + xv.y + xv.z + xv.w;
    float s2 = xv.x*xv.x + xv.y*xv.y + xv.z*xv.z + xv.w*xv.w;
    #pragma unroll
    for (int o = 16; o; o >>= 1) {
        s  += __shfl_xor_sync(0xffffffffu, s, o);
        s2 += __shfl_xor_sync(0xffffffffu, s2, o);
    }
    __shared__ float sh[8];
    int w = tid >> 5;
    if ((tid & 31) == 0) { sh[w] = s; sh[4 + w] = s2; }
    __syncthreads();
    s  = sh[0] + sh[1] + sh[2] + sh[3];
    s2 = sh[4] + sh[5] + sh[6] + sh[7];
    float mu  = s * (1.0f / DMODEL);
    float var = s2 * (1.0f / DMODEL) - mu * mu;
    float inv = rsqrtf(var + 1e-5f);
    float4 gv = ((const float4*)lng)[tid];
    float4 bv = ((const float4*)lnb)[tid];
    float4 hv;
    hv.x = (xv.x - mu) * inv * gv.x + bv.x;
    hv.y = (xv.y - mu) * inv * gv.y + bv.y;
    hv.z = (xv.z - mu) * inv * gv.z + bv.z;
    hv.w = (xv.w - mu) * inv * gv.w + bv.w;
    ((float4*)(g_x + (size_t)t * DMODEL))[tid] = xv;
    ((float4*)(g_h + (size_t)t * DMODEL))[tid] = hv;
}

// ---------------- K2: compose via bf16 two-plane mma ----------------
// 256 threads = 8 warps (4 row-groups x 2 n-halves). 64 rows/block.
__global__ __launch_bounds__(256, 2) void k_compose(
    const float* __restrict__ pq, const float* __restrict__ gq,
    const float* __restrict__ pk, const float* __restrict__ gk,
    const float* __restrict__ pv, const float* __restrict__ gv,
    const float* __restrict__ w1, const float* __restrict__ w2) {
    extern __shared__ __align__(16) unsigned short smc[];
    unsigned short* Xh  = smc;               // 64 x 72
    unsigned short* Xl  = Xh  + 64 * STR;
    unsigned short* W1h = Xl  + 64 * STR;
    unsigned short* W1l = W1h + 64 * STR;
    unsigned short* W2h = W1l + 64 * STR;
    unsigned short* W2l = W2h + 64 * STR;
    unsigned short* Sh  = W2l + 64 * STR;
    unsigned short* Sl  = Sh  + 64 * STR;
    float* WG = (float*)(Sl + 64 * STR);     // 3 x 64 x 16

    const int tid = threadIdx.x, warp = tid >> 5, lane = tid & 31;
    const int g = lane >> 2, tg = lane & 3;
    const int mi0 = (lane >> 3) & 1;   // k-half selector for ldmatrix
    const int mi1 = lane >> 4;         // n-offset selector
    const int r8 = lane & 7;
    const int wy = warp >> 1, wx = warp & 1;
    const int wr0 = wy * 16, nc0 = wx * 32;
    const int row0 = blockIdx.x * 64;

    unsigned* Xhw = (unsigned*)Xh; unsigned* Xlw = (unsigned*)Xl;
    unsigned* Shw = (unsigned*)Sh; unsigned* Slw = (unsigned*)Sl;
    unsigned* W1hw = (unsigned*)W1h; unsigned* W1lw = (unsigned*)W1l;
    unsigned* W2hw = (unsigned*)W2h; unsigned* W2lw = (unsigned*)W2l;

    // fill X planes
    #pragma unroll
    for (int i = tid; i < 64 * 16; i += 256) {
        int r = i >> 4, c = i & 15;
        float4 v = ((const float4*)(g_h + (size_t)(row0 + r) * 64))[c];
        unsigned h0, l0, h1, l1;
        split2(v.x, v.y, h0, l0);
        split2(v.z, v.w, h1, l1);
        Xhw[r * WSTR + 2 * c] = h0; Xhw[r * WSTR + 2 * c + 1] = h1;
        Xlw[r * WSTR + 2 * c] = l0; Xlw[r * WSTR + 2 * c + 1] = l1;
    }

    // gate weights (fp32, from gmem; rows L1-resident)
    for (int i = tid; i < 64 * 16; i += 256) {
        int r = i >> 4, p = i & 15;
        const float* xr = g_h + (size_t)(row0 + r) * 64;
        float dq = 0.f, dk = 0.f, dv = 0.f;
        #pragma unroll 8
        for (int d = 0; d < 64; ++d) {
            float xv = __ldg(xr + d);
            dq += xv * pq[p * 64 + d];
            dk += xv * pk[p * 64 + d];
            dv += xv * pv[p * 64 + d];
        }
        float lq = dq * 0.125f - gq[p];
        float lk = dk * 0.125f - gk[p];
        float lv = dv * 0.125f - gv[p];
        WG[(0 * 64 + r) * 16 + p] = lq > 1e-6f ? lq : 0.f;
        WG[(1 * 64 + r) * 16 + p] = lk > 1e-6f ? lk : 0.f;
        WG[(2 * 64 + r) * 16 + p] = lv > 1e-6f ? lv : 0.f;
    }

    float aq[16], ak[16], av[16];
    #pragma unroll
    for (int i = 0; i < 16; ++i) { aq[i] = 0.f; ak[i] = 0.f; av[i] = 0.f; }

    const float LOG2E = 1.44269504f;

    for (int p = 0; p < NP; ++p) {
        __syncthreads();
        // fill W1, W2 planes
        #pragma unroll
        for (int i = tid; i < 64 * 16; i += 256) {
            int r = i >> 4, c = i & 15;
            float4 a = ((const float4*)(w1 + (size_t)p * 4096 + r * 64))[c];
            float4 b = ((const float4*)(w2 + (size_t)p * 4096 + r * 64))[c];
            unsigned h0, l0, h1, l1;
            split2(a.x, a.y, h0, l0); split2(a.z, a.w, h1, l1);
            W1hw[r * WSTR + 2 * c] = h0; W1hw[r * WSTR + 2 * c + 1] = h1;
            W1lw[r * WSTR + 2 * c] = l0; W1lw[r * WSTR + 2 * c + 1] = l1;
            split2(b.x, b.y, h0, l0); split2(b.z, b.w, h1, l1);
            W2hw[r * WSTR + 2 * c] = h0; W2hw[r * WSTR + 2 * c + 1] = h1;
            W2lw[r * WSTR + 2 * c] = l0; W2lw[r * WSTR + 2 * c + 1] = l1;
        }
        __syncthreads();

        // GEMM1: H = X @ W1^T  (warp: 16 rows x 32 cols)
        float hb[16];
        #pragma unroll
        for (int i = 0; i < 16; ++i) hb[i] = 0.f;
        #pragma unroll
        for (int ks = 0; ks < 4; ++ks) {
            unsigned ah[4], al[4];
            ah[0] = Xhw[(wr0 + g)     * WSTR + 8 * ks + tg];
            ah[1] = Xhw[(wr0 + g + 8) * WSTR + 8 * ks + tg];
            ah[2] = Xhw[(wr0 + g)     * WSTR + 8 * ks + 4 + tg];
            ah[3] = Xhw[(wr0 + g + 8) * WSTR + 8 * ks + 4 + tg];
            al[0] = Xlw[(wr0 + g)     * WSTR + 8 * ks + tg];
            al[1] = Xlw[(wr0 + g + 8) * WSTR + 8 * ks + tg];
            al[2] = Xlw[(wr0 + g)     * WSTR + 8 * ks + 4 + tg];
            al[3] = Xlw[(wr0 + g + 8) * WSTR + 8 * ks + 4 + tg];
            #pragma unroll
            for (int np = 0; np < 2; ++np) {
                int roff = (nc0 + np * 16 + mi1 * 8 + r8) * STR + ks * 16 + mi0 * 8;
                unsigned bh[4], bl[4];
                ldm_x4(bh, W1h + roff);
                ldm_x4(bl, W1l + roff);
                mma3(&hb[(np * 2) * 4],     ah, al, bh[0], bh[1], bl[0], bl[1]);
                mma3(&hb[(np * 2 + 1) * 4], ah, al, bh[2], bh[3], bl[2], bl[3]);
            }
        }
        // silu -> S planes
        #pragma unroll
        for (int nt = 0; nt < 4; ++nt) {
            #pragma unroll
            for (int j = 0; j < 4; ++j) {
                float h = hb[nt * 4 + j];
                hb[nt * 4 + j] = h / (1.f + fast_exp2(-h * LOG2E));
            }
            unsigned h0, l0;
            split2(hb[nt * 4 + 0], hb[nt * 4 + 1], h0, l0);
            Shw[(wr0 + g) * WSTR + nc0 / 2 + 4 * nt + tg] = h0;
            Slw[(wr0 + g) * WSTR + nc0 / 2 + 4 * nt + tg] = l0;
            split2(hb[nt * 4 + 2], hb[nt * 4 + 3], h0, l0);
            Shw[(wr0 + g + 8) * WSTR + nc0 / 2 + 4 * nt + tg] = h0;
            Slw[(wr0 + g + 8) * WSTR + nc0 / 2 + 4 * nt + tg] = l0;
        }
        __syncthreads();

        // GEMM2: out = silu(H) @ W2^T
        float ob[16];
        #pragma unroll
        for (int i = 0; i < 16; ++i) ob[i] = 0.f;
        #pragma unroll
        for (int ks = 0; ks < 4; ++ks) {
            unsigned ah[4], al[4];
            ah[0] = Shw[(wr0 + g)     * WSTR + 8 * ks + tg];
            ah[1] = Shw[(wr0 + g + 8) * WSTR + 8 * ks + tg];
            ah[2] = Shw[(wr0 + g)     * WSTR + 8 * ks + 4 + tg];
            ah[3] = Shw[(wr0 + g + 8) * WSTR + 8 * ks + 4 + tg];
            al[0] = Slw[(wr0 + g)     * WSTR + 8 * ks + tg];
            al[1] = Slw[(wr0 + g + 8) * WSTR + 8 * ks + tg];
            al[2] = Slw[(wr0 + g)     * WSTR + 8 * ks + 4 + tg];
            al[3] = Slw[(wr0 + g + 8) * WSTR + 8 * ks + 4 + tg];
            #pragma unroll
            for (int np = 0; np < 2; ++np) {
                int roff = (nc0 + np * 16 + mi1 * 8 + r8) * STR + ks * 16 + mi0 * 8;
                unsigned bh[4], bl[4];
                ldm_x4(bh, W2h + roff);
                ldm_x4(bl, W2l + roff);
                mma3(&ob[(np * 2) * 4],     ah, al, bh[0], bh[1], bl[0], bl[1]);
                mma3(&ob[(np * 2 + 1) * 4], ah, al, bh[2], bh[3], bl[2], bl[3]);
            }
        }
        // gated accumulate
        float wq0 = WG[(0 * 64 + wr0 + g)     * 16 + p];
        float wq1 = WG[(0 * 64 + wr0 + g + 8) * 16 + p];
        float wk0 = WG[(1 * 64 + wr0 + g)     * 16 + p];
        float wk1 = WG[(1 * 64 + wr0 + g + 8) * 16 + p];
        float wv0 = WG[(2 * 64 + wr0 + g)     * 16 + p];
        float wv1 = WG[(2 * 64 + wr0 + g + 8) * 16 + p];
        #pragma unroll
        for (int nt = 0; nt < 4; ++nt) {
            aq[nt*4+0] += wq0 * ob[nt*4+0]; aq[nt*4+1] += wq0 * ob[nt*4+1];
            aq[nt*4+2] += wq1 * ob[nt*4+2]; aq[nt*4+3] += wq1 * ob[nt*4+3];
            ak[nt*4+0] += wk0 * ob[nt*4+0]; ak[nt*4+1] += wk0 * ob[nt*4+1];
            ak[nt*4+2] += wk1 * ob[nt*4+2]; ak[nt*4+3] += wk1 * ob[nt*4+3];
            av[nt*4+0] += wv0 * ob[nt*4+0]; av[nt*4+1] += wv0 * ob[nt*4+1];
            av[nt*4+2] += wv1 * ob[nt*4+2]; av[nt*4+3] += wv1 * ob[nt*4+3];
        }
    }

    // write q,k,v to [bh][t][64]
    int r_lo = row0 + wr0 + g;
    int r_hi = r_lo + 8;
    int tok_lo = r_lo >> 3, h_lo = r_lo & 7;
    int tok_hi = r_hi >> 3, h_hi = r_hi & 7;
    int b_lo = tok_lo >> 11, t_lo = tok_lo & 2047;
    int b_hi = tok_hi >> 11, t_hi = tok_hi & 2047;
    size_t base_lo = ((size_t)(b_lo * 8 + h_lo) * NT + t_lo) * 64;
    size_t base_hi = ((size_t)(b_hi * 8 + h_hi) * NT + t_hi) * 64;
    #pragma unroll
    for (int nt = 0; nt < 4; ++nt) {
        int col = nc0 + nt * 8 + 2 * tg;
        *(float2*)&g_q[base_lo + col] = make_float2(aq[nt*4+0], aq[nt*4+1]);
        *(float2*)&g_q[base_hi + col] = make_float2(aq[nt*4+2], aq[nt*4+3]);
        *(float2*)&g_k[base_lo + col] = make_float2(ak[nt*4+0], ak[nt*4+1]);
        *(float2*)&g_k[base_hi + col] = make_float2(ak[nt*4+2], ak[nt*4+3]);
        *(float2*)&g_v[base_lo + col] = make_float2(av[nt*4+0], av[nt*4+1]);
        *(float2*)&g_v[base_hi + col] = make_float2(av[nt*4+2], av[nt*4+3]);
    }
}

// ---------------- K3: flash attention via bf16 two-plane mma ----------------
// 128 threads = 4 warps x 16 q rows; 64-row Q tile, 64-row K tile.
__global__ __launch_bounds__(128) void k_attn() {
    extern __shared__ __align__(16) unsigned short sma[];
    unsigned short* Kh = sma;              // 64 x 72
    unsigned short* Kl = Kh + 64 * STR;
    unsigned short* Vh = Kl + 64 * STR;
    unsigned short* Vl = Vh + 64 * STR;
    unsigned* Khw = (unsigned*)Kh; unsigned* Klw = (unsigned*)Kl;
    unsigned* Vhw = (unsigned*)Vh; unsigned* Vlw = (unsigned*)Vl;

    const int tid = threadIdx.x, warp = tid >> 5, lane = tid & 31;
    const int g = lane >> 2, tg = lane & 3;
    const int mi0 = (lane >> 3) & 1;
    const int mi1 = lane >> 4;
    const int r8 = lane & 7;
    const int qtile = 31 - blockIdx.x;   // biggest first
    const int qt0 = qtile * 64;
    const int bh = blockIdx.y;
    const int b = bh >> 3, h = bh & 7;
    const float* qbase = g_q + (size_t)bh * NT * 64;
    const float* kbase = g_k + (size_t)bh * NT * 64;
    const float* vbase = g_v + (size_t)bh * NT * 64;
    const int wr0 = warp * 16;

    // persistent Q fragments
    unsigned Qh[4][4], Ql[4][4];
    {
        const float* qr0 = qbase + (size_t)(qt0 + wr0 + g) * 64 + 2 * tg;
        const float* qr1 = qbase + (size_t)(qt0 + wr0 + g + 8) * 64 + 2 * tg;
        #pragma unroll
        for (int ks = 0; ks < 4; ++ks) {
            float2 v;
            v = *(const float2*)(qr0 + 16 * ks);     split2(v.x, v.y, Qh[ks][0], Ql[ks][0]);
            v = *(const float2*)(qr1 + 16 * ks);     split2(v.x, v.y, Qh[ks][1], Ql[ks][1]);
            v = *(const float2*)(qr0 + 16 * ks + 8); split2(v.x, v.y, Qh[ks][2], Ql[ks][2]);
            v = *(const float2*)(qr1 + 16 * ks + 8); split2(v.x, v.y, Qh[ks][3], Ql[ks][3]);
        }
    }

    float O[32];
    #pragma unroll
    for (int i = 0; i < 32; ++i) O[i] = 0.f;
    float m2[2] = {-1e30f, -1e30f};
    float l2[2] = {0.f, 0.f};
    const float sc = 0.125f * 1.44269504f;  // /sqrt(64) * log2(e)

    for (int kt = 0; kt <= qtile; ++kt) {
        __syncthreads();
        #pragma unroll
        for (int i = tid; i < 64 * 16; i += 128) {
            int r = i >> 4, c = i & 15;
            size_t base = (size_t)(kt * 64 + r) * 64 + 4 * c;
            float4 kv = *(const float4*)(kbase + base);
            float4 vv = *(const float4*)(vbase + base);
            unsigned h0, l0, h1, l1;
            split2(kv.x, kv.y, h0, l0); split2(kv.z, kv.w, h1, l1);
            Khw[r * WSTR + 2 * c] = h0; Khw[r * WSTR + 2 * c + 1] = h1;
            Klw[r * WSTR + 2 * c] = l0; Klw[r * WSTR + 2 * c + 1] = l1;
            split2(vv.x, vv.y, h0, l0); split2(vv.z, vv.w, h1, l1);
            Vhw[r * WSTR + 2 * c] = h0; Vhw[r * WSTR + 2 * c + 1] = h1;
            Vlw[r * WSTR + 2 * c] = l0; Vlw[r * WSTR + 2 * c + 1] = l1;
        }
        __syncthreads();

        const bool diag = (kt == qtile);
        const int npmax = diag ? warp : 3;

        // S = Q K^T
        float s[32];
        #pragma unroll
        for (int i = 0; i < 32; ++i) s[i] = 0.f;
        #pragma unroll
        for (int ks = 0; ks < 4; ++ks) {
            for (int np = 0; np <= npmax; ++np) {
                int roff = (np * 16 + mi1 * 8 + r8) * STR + ks * 16 + mi0 * 8;
                unsigned bh4[4], bl4[4];
                ldm_x4(bh4, Kh + roff);
                ldm_x4(bl4, Kl + roff);
                mma3(&s[(np * 2) * 4],     Qh[ks], Ql[ks], bh4[0], bh4[1], bl4[0], bl4[1]);
                mma3(&s[(np * 2 + 1) * 4], Qh[ks], Ql[ks], bh4[2], bh4[3], bl4[2], bl4[3]);
            }
        }
        // scale + causal mask (base-2 domain)
        #pragma unroll
        for (int nt = 0; nt < 8; ++nt)
            #pragma unroll
            for (int j = 0; j < 4; ++j) {
                int rr = qt0 + wr0 + g + (j >> 1) * 8;
                int cc = kt * 64 + nt * 8 + 2 * tg + (j & 1);
                float v = s[nt * 4 + j] * sc;
                if (diag && cc > rr) v = -1e30f;
                s[nt * 4 + j] = v;
            }
        // online softmax (2 rows/thread; 4 lanes share a row)
        #pragma unroll
        for (int h2 = 0; h2 < 2; ++h2) {
            float mx = -1e30f;
            #pragma unroll
            for (int nt = 0; nt < 8; ++nt) {
                mx = fmaxf(mx, s[nt * 4 + h2 * 2 + 0]);
                mx = fmaxf(mx, s[nt * 4 + h2 * 2 + 1]);
            }
            mx = fmaxf(mx, __shfl_xor_sync(0xffffffffu, mx, 1));
            mx = fmaxf(mx, __shfl_xor_sync(0xffffffffu, mx, 2));
            float mn = fmaxf(m2[h2], mx);
            float alpha = fast_exp2(m2[h2] - mn);
            m2[h2] = mn;
            float rs = 0.f;
            #pragma unroll
            for (int nt = 0; nt < 8; ++nt) {
                float p0 = fast_exp2(s[nt * 4 + h2 * 2 + 0] - mn);
                float p1 = fast_exp2(s[nt * 4 + h2 * 2 + 1] - mn);
                s[nt * 4 + h2 * 2 + 0] = p0;
                s[nt * 4 + h2 * 2 + 1] = p1;
                rs += p0 + p1;
            }
            rs += __shfl_xor_sync(0xffffffffu, rs, 1);
            rs += __shfl_xor_sync(0xffffffffu, rs, 2);
            l2[h2] = l2[h2] * alpha + rs;
            #pragma unroll
            for (int nt = 0; nt < 8; ++nt) {
                O[nt * 4 + h2 * 2 + 0] *= alpha;
                O[nt * 4 + h2 * 2 + 1] *= alpha;
            }
        }
        // O += P V   (P fragments straight from registers: k16 A-frag = two n8 C-frags)
        const int ksmax = diag ? warp : 3;
        #pragma unroll
        for (int ks = 0; ks < 4; ++ks) {
            if (ks > ksmax) break;
            unsigned pah[4], pal[4];
            split2(s[8 * ks + 0], s[8 * ks + 1], pah[0], pal[0]);
            split2(s[8 * ks + 2], s[8 * ks + 3], pah[1], pal[1]);
            split2(s[8 * ks + 4], s[8 * ks + 5], pah[2], pal[2]);
            split2(s[8 * ks + 6], s[8 * ks + 7], pah[3], pal[3]);
            #pragma unroll
            for (int np = 0; np < 4; ++np) {
                int roff = (ks * 16 + mi0 * 8 + r8) * STR + np * 16 + mi1 * 8;
                unsigned vh4[4], vl4[4];
                ldm_x4_t(vh4, Vh + roff);
                ldm_x4_t(vl4, Vl + roff);
                mma3(&O[(np * 2) * 4],     pah, pal, vh4[0], vh4[1], vl4[0], vl4[1]);
                mma3(&O[(np * 2 + 1) * 4], pah, pal, vh4[2], vh4[3], vl4[2], vl4[3]);
            }
        }
    }

    float inv0 = 1.f / l2[0];
    float inv1 = 1.f / l2[1];
    int r_lo = qt0 + wr0 + g;
    int r_hi = r_lo + 8;
    size_t base_lo = ((size_t)(b * NT + r_lo) * 8 + h) * 64;
    size_t base_hi = ((size_t)(b * NT + r_hi) * 8 + h) * 64;
    #pragma unroll
    for (int nt = 0; nt < 8; ++nt) {
        int col = nt * 8 + 2 * tg;
        *(float2*)&g_attn[base_lo + col] =
            make_float2(O[nt*4+0] * inv0, O[nt*4+1] * inv0);
        *(float2*)&g_attn[base_hi + col] =
            make_float2(O[nt*4+2] * inv1, O[nt*4+3] * inv1);
    }
}

// ---------------- K4: logits = x@head_w^T + attn@C ----------------
__global__ __launch_bounds__(128) void k_final(const float* __restrict__ head_w,
                                               float* __restrict__ out) {
    int t = blockIdx.x;
    int tid = threadIdx.x;
    int v = tid & 15, ch = tid >> 4;
    const float* xr = g_x + (size_t)t * DMODEL;
    const float* ar = g_attn + (size_t)t * DMODEL;
    float acc = 0.f;
    int d0 = ch * 64;
    #pragma unroll 8
    for (int d = d0; d < d0 + 64; ++d)
        acc += xr[d] * head_w[v * DMODEL + d] + ar[d] * g_C[d * NVOC + v];
    __shared__ float red[128];
    red[tid] = acc;
    __syncthreads();
    if (ch == 0) {
        float s = 0.f;
        #pragma unroll
        for (int c = 0; c < 8; ++c) s += red[c * 16 + v];
        out[(size_t)t * NVOC + v] = s;
    }
}

// ---------------- launch ----------------
extern "C" void kernel_launch(void* const* d_in, const int* in_sizes, int n_in,
                              void* d_out, int out_size) {
    const int*   ids    = (const int*)d_in[0];
    const float* embed  = (const float*)d_in[1];
    const float* ln_g   = (const float*)d_in[2];
    const float* ln_b   = (const float*)d_in[3];
    const float* pq     = (const float*)d_in[4];
    const float* gq     = (const float*)d_in[5];
    const float* pk     = (const float*)d_in[6];
    const float* gk     = (const float*)d_in[7];
    const float* pv     = (const float*)d_in[8];
    const float* gv     = (const float*)d_in[9];
    const float* w1     = (const float*)d_in[10];
    const float* w2     = (const float*)d_in[11];
    const float* o_w    = (const float*)d_in[12];
    const float* head_w = (const float*)d_in[13];
    float* out = (float*)d_out;

    const int smem_compose = 8 * 64 * STR * 2 + 3 * 64 * 16 * 4;  // 86016 B
    const int smem_attn    = 4 * 64 * STR * 2;                    // 36864 B
    cudaFuncSetAttribute(k_compose, cudaFuncAttributeMaxDynamicSharedMemorySize, smem_compose);
    cudaFuncSetAttribute(k_attn,    cudaFuncAttributeMaxDynamicSharedMemorySize, smem_attn);

    k_compute_C<<<32, 256>>>(o_w, head_w);
    k_embed_ln<<<NTOK, 128>>>(ids, embed, ln_g, ln_b);
    k_compose<<<NTH / 64, 256, smem_compose>>>(pq, gq, pk, gk, pv, gv, w1, w2);
    dim3 ag(NT / 64, NB * NHEAD);
    k_attn<<<ag, 128, smem_attn>>>();
    k_final<<<NTOK, 128>>>(head_w, out);
}